// round 2
// baseline (speedup 1.0000x reference)
#include <cuda_runtime.h>
#include <math.h>

// ---------------- problem constants ----------------
#define B_ROWS 16384
#define IN_DIM 768
#define ENC_DIM 500
#define KCLS 43
#define VDIM 1024
#define CAT_RAW 1067          // VDIM + KCLS
#define CAT_LD  1080          // padded, multiple of 8 floats (16B aligned rows)

// ---------------- scratch (static device globals: no allocation) ----------------
__device__ float g_h  [(size_t)B_ROWS * VDIM];        // relu(x@W1^T)
__device__ float g_ml [(size_t)B_ROWS * 2 * VDIM];    // mu||logvar
__device__ float g_cat[(size_t)B_ROWS * CAT_LD];      // [sampled_z | y | 0pad]
__device__ float g_Wd [(size_t)IN_DIM * CAT_LD];      // padded decoder weight
__device__ float g_klp[B_ROWS];                        // per-row KL partials
__device__ float g_ze_s[(size_t)B_ROWS * ENC_DIM];     // fallback scratch
__device__ float g_zq_s[(size_t)B_ROWS * ENC_DIM];
__device__ float g_lg_s[(size_t)B_ROWS * KCLS];
__device__ float g_kl_s[1];
__device__ int   g_mask_mode;                          // 0=bool bytes,1=int32,2=float32

// ---------------- generic TN SGEMM: C[M,N] = A[M,K] @ B[N,K]^T (+bias)(+relu) ----------------
#define BM 128
#define BN 128
#define BK 16

template<bool RELU>
__global__ __launch_bounds__(256, 2)
void sgemm_tn(const float* __restrict__ A, int lda,
              const float* __restrict__ Bm, int ldb,
              const float* __restrict__ bias,
              float* __restrict__ C, int ldc,
              int M, int N, int K)
{
    __shared__ float As[BK][BM];
    __shared__ float Bs[BK][BN];

    const int tid = threadIdx.x;
    const int m0 = blockIdx.y * BM;
    const int n0 = blockIdx.x * BN;
    const int tx = tid & 15;
    const int ty = tid >> 4;

    float acc[8][8];
#pragma unroll
    for (int i = 0; i < 8; i++)
#pragma unroll
        for (int j = 0; j < 8; j++) acc[i][j] = 0.f;

    const int lrow = tid >> 2;        // 0..63 (two halves: +0, +64)
    const int lkq  = (tid & 3) * 4;   // 0,4,8,12

    for (int k0 = 0; k0 < K; k0 += BK) {
        // ---- load A tile (transposed into As[k][m]) ----
#pragma unroll
        for (int h = 0; h < 2; h++) {
            int row = lrow + h * 64;
            int gr = m0 + row;
            int kk = k0 + lkq;
            float4 v = make_float4(0.f, 0.f, 0.f, 0.f);
            if (gr < M) {
                const float* p = A + (size_t)gr * lda + kk;
                if (kk + 3 < K) v = *reinterpret_cast<const float4*>(p);
                else {
                    if (kk + 0 < K) v.x = p[0];
                    if (kk + 1 < K) v.y = p[1];
                    if (kk + 2 < K) v.z = p[2];
                    if (kk + 3 < K) v.w = p[3];
                }
            }
            As[lkq + 0][row] = v.x;
            As[lkq + 1][row] = v.y;
            As[lkq + 2][row] = v.z;
            As[lkq + 3][row] = v.w;
        }
        // ---- load B tile ----
#pragma unroll
        for (int h = 0; h < 2; h++) {
            int row = lrow + h * 64;
            int gr = n0 + row;
            int kk = k0 + lkq;
            float4 v = make_float4(0.f, 0.f, 0.f, 0.f);
            if (gr < N) {
                const float* p = Bm + (size_t)gr * ldb + kk;
                if (kk + 3 < K) v = *reinterpret_cast<const float4*>(p);
                else {
                    if (kk + 0 < K) v.x = p[0];
                    if (kk + 1 < K) v.y = p[1];
                    if (kk + 2 < K) v.z = p[2];
                    if (kk + 3 < K) v.w = p[3];
                }
            }
            Bs[lkq + 0][row] = v.x;
            Bs[lkq + 1][row] = v.y;
            Bs[lkq + 2][row] = v.z;
            Bs[lkq + 3][row] = v.w;
        }
        __syncthreads();

#pragma unroll
        for (int k = 0; k < BK; k++) {
            float4 a0 = *reinterpret_cast<const float4*>(&As[k][ty * 4]);
            float4 a1 = *reinterpret_cast<const float4*>(&As[k][64 + ty * 4]);
            float4 b0 = *reinterpret_cast<const float4*>(&Bs[k][tx * 4]);
            float4 b1 = *reinterpret_cast<const float4*>(&Bs[k][64 + tx * 4]);
            float a[8] = {a0.x, a0.y, a0.z, a0.w, a1.x, a1.y, a1.z, a1.w};
            float b[8] = {b0.x, b0.y, b0.z, b0.w, b1.x, b1.y, b1.z, b1.w};
#pragma unroll
            for (int i = 0; i < 8; i++)
#pragma unroll
                for (int j = 0; j < 8; j++)
                    acc[i][j] = fmaf(a[i], b[j], acc[i][j]);
        }
        __syncthreads();
    }

    // ---- epilogue ----
#pragma unroll
    for (int i = 0; i < 8; i++) {
        int row = m0 + ((i < 4) ? (ty * 4 + i) : (64 + ty * 4 + i - 4));
        if (row >= M) continue;
#pragma unroll
        for (int j = 0; j < 8; j++) {
            int col = n0 + ((j < 4) ? (tx * 4 + j) : (64 + tx * 4 + j - 4));
            if (col < N) {
                float v = acc[i][j];
                if (bias) v += bias[col];
                if (RELU) v = fmaxf(v, 0.f);
                C[(size_t)row * ldc + col] = v;
            }
        }
    }
}

// ---------------- pack Wd (768 x 1067) into padded (768 x 1080) ----------------
__global__ void pack_wd_kernel(const float* __restrict__ Wd)
{
    int idx = blockIdx.x * blockDim.x + threadIdx.x;
    const int total = IN_DIM * CAT_LD;
    if (idx >= total) return;
    int r = idx / CAT_LD;
    int c = idx - r * CAT_LD;
    g_Wd[idx] = (c < CAT_RAW) ? Wd[(size_t)r * CAT_RAW + c] : 0.f;
}

// ---------------- detect known_mask dtype (bool bytes vs int32 vs float32) ----------------
__global__ void detect_mask_kernel(const unsigned int* __restrict__ w)
{
    __shared__ int s_int, s_flt;
    if (threadIdx.x == 0) { s_int = 1; s_flt = 1; }
    __syncthreads();
    int li = 1, lf = 1;
    // 4096 words = 16KB, valid under every dtype interpretation of 16384 elements
    for (int i = threadIdx.x; i < 4096; i += blockDim.x) {
        unsigned v = w[i];
        if (v > 1u) li = 0;
        if (v != 0u && v != 0x3F800000u) lf = 0;
    }
    if (!li) atomicAnd(&s_int, 0);
    if (!lf) atomicAnd(&s_flt, 0);
    __syncthreads();
    if (threadIdx.x == 0) g_mask_mode = s_int ? 1 : (s_flt ? 2 : 0);
}

// ---------------- argmax + softmax(y) + codebook gather; one warp per row ----------------
__global__ void argmax_y_kernel(const float* __restrict__ logits,
                                const void*  __restrict__ mask,
                                const int*   __restrict__ labels,
                                const float* __restrict__ codebook,
                                float* __restrict__ zq)
{
    const int b = blockIdx.x;
    const int lane = threadIdx.x;
    const float NEG_INF = __int_as_float(0xff800000u);

    const float* lr = logits + (size_t)b * KCLS;
    float v0 = (lane < KCLS) ? lr[lane] : NEG_INF;
    float v1 = (lane + 32 < KCLS) ? lr[lane + 32] : NEG_INF;

    float m; int mi;
    if (v0 >= v1) { m = v0; mi = lane; } else { m = v1; mi = lane + 32; }
#pragma unroll
    for (int off = 16; off > 0; off >>= 1) {
        float om = __shfl_xor_sync(0xffffffffu, m, off);
        int   oi = __shfl_xor_sync(0xffffffffu, mi, off);
        if (om > m || (om == m && oi < mi)) { m = om; mi = oi; }
    }

    float e0 = (lane < KCLS) ? expf(v0 - m) : 0.f;
    float e1 = (lane + 32 < KCLS) ? expf(v1 - m) : 0.f;
    float s = e0 + e1;
#pragma unroll
    for (int off = 16; off > 0; off >>= 1)
        s += __shfl_xor_sync(0xffffffffu, s, off);
    float inv = 1.0f / s;

    int mode = g_mask_mode;
    bool known;
    if (mode == 1)      known = ((const int*)mask)[b] != 0;
    else if (mode == 2) known = ((const float*)mask)[b] != 0.f;
    else                known = ((const unsigned char*)mask)[b] != 0;
    int lab = labels[b];

    float* yr = g_cat + (size_t)b * CAT_LD + VDIM;   // 56 slots (43 real + pad)
    {
        int k = lane;
        float val = (k < KCLS) ? (known ? (k == lab ? 1.f : 0.f) : e0 * inv) : 0.f;
        yr[k] = val;
        k = lane + 32;
        if (k < CAT_LD - VDIM) {
            float val2 = (k < KCLS) ? (known ? (k == lab ? 1.f : 0.f) : e1 * inv) : 0.f;
            yr[k] = val2;
        }
    }

    const float* cr = codebook + (size_t)mi * ENC_DIM;
    float* zr = zq + (size_t)b * ENC_DIM;
    for (int i = lane; i < ENC_DIM; i += 32) zr[i] = cr[i];
}

// ---------------- reparam sample + per-row KL partial ----------------
__global__ void vae_post_kernel(const float* __restrict__ eps)
{
    const int b = blockIdx.x;
    const int t = threadIdx.x;
    const float* mlr = g_ml + (size_t)b * (2 * VDIM);
    const float* er  = eps + (size_t)b * VDIM;
    float* zr = g_cat + (size_t)b * CAT_LD;

    float kl = 0.f;
    for (int i = t; i < VDIM; i += 256) {
        float mu = mlr[i];
        float lv = mlr[VDIM + i];
        float elv = expf(lv);
        kl += 0.5f * (elv + mu * mu - 1.0f - lv);
        zr[i] = fmaf(expf(0.5f * lv), er[i], mu);
    }
    __shared__ float sm[256];
    sm[t] = kl;
    __syncthreads();
    for (int st = 128; st > 0; st >>= 1) {
        if (t < st) sm[t] += sm[t + st];
        __syncthreads();
    }
    if (t == 0) g_klp[b] = sm[0];
}

// ---------------- deterministic final KL reduction ----------------
__global__ void kl_reduce_kernel(float* __restrict__ out)
{
    const int t = threadIdx.x;
    float s = 0.f;
    for (int i = t; i < B_ROWS; i += 256) s += g_klp[i];
    __shared__ float sm[256];
    sm[t] = s;
    __syncthreads();
    for (int st = 128; st > 0; st >>= 1) {
        if (t < st) sm[t] += sm[t + st];
        __syncthreads();
    }
    if (t == 0) *out = sm[0] / (float)B_ROWS;
}

// ---------------- host-side GEMM launcher ----------------
static void launch_gemm(const float* A, int lda, const float* Bm, int ldb,
                        const float* bias, float* C, int ldc,
                        int M, int N, int K, bool relu)
{
    dim3 grid((N + BN - 1) / BN, (M + BM - 1) / BM);
    if (relu) sgemm_tn<true ><<<grid, 256>>>(A, lda, Bm, ldb, bias, C, ldc, M, N, K);
    else      sgemm_tn<false><<<grid, 256>>>(A, lda, Bm, ldb, bias, C, ldc, M, N, K);
}

extern "C" void kernel_launch(void* const* d_in, const int* in_sizes, int n_in,
                              void* d_out, int out_size)
{
    const float* x        = (const float*)d_in[0];
    const void*  mask     = d_in[1];
    const int*   labels   = (const int*)d_in[2];
    const float* eps      = (const float*)d_in[3];
    const float* W_enc    = (const float*)d_in[4];
    const float* b_enc    = (const float*)d_in[5];
    const float* codebook = (const float*)d_in[6];
    const float* W1       = (const float*)d_in[7];
    const float* b1       = (const float*)d_in[8];
    const float* W2       = (const float*)d_in[9];
    const float* b2       = (const float*)d_in[10];
    const float* Wd       = (const float*)d_in[11];
    const float* bd       = (const float*)d_in[12];

    float* out = (float*)d_out;

    // scratch symbol addresses (query each call; capture-safe, non-stream API)
    float *p_h, *p_ml, *p_cat, *p_wd, *p_ze_s, *p_zq_s, *p_lg_s, *p_kl_s;
    cudaGetSymbolAddress((void**)&p_h,    g_h);
    cudaGetSymbolAddress((void**)&p_ml,   g_ml);
    cudaGetSymbolAddress((void**)&p_cat,  g_cat);
    cudaGetSymbolAddress((void**)&p_wd,   g_Wd);
    cudaGetSymbolAddress((void**)&p_ze_s, g_ze_s);
    cudaGetSymbolAddress((void**)&p_zq_s, g_zq_s);
    cudaGetSymbolAddress((void**)&p_lg_s, g_lg_s);
    cudaGetSymbolAddress((void**)&p_kl_s, g_kl_s);

    // output layout: tuple (x_tilde, z_e_x, z_q_x, logits, kl_div) flattened.
    const size_t full_elems = (size_t)B_ROWS * (IN_DIM + ENC_DIM + ENC_DIM + KCLS) + 1;
    const bool full = ((size_t)out_size >= full_elems);
    float* xt = out;
    float* ze = full ? out + (size_t)B_ROWS * IN_DIM : p_ze_s;
    float* zq = full ? ze + (size_t)B_ROWS * ENC_DIM : p_zq_s;
    float* lg = full ? zq + (size_t)B_ROWS * ENC_DIM : p_lg_s;
    float* kl = full ? lg + (size_t)B_ROWS * KCLS    : p_kl_s;

    // independent prep
    pack_wd_kernel<<<(IN_DIM * CAT_LD + 255) / 256, 256>>>(Wd);
    detect_mask_kernel<<<1, 256>>>((const unsigned int*)mask);

    // encoder
    launch_gemm(x, IN_DIM, W_enc, IN_DIM, b_enc, ze, ENC_DIM, B_ROWS, ENC_DIM, IN_DIM, false);
    // logits
    launch_gemm(ze, ENC_DIM, codebook, ENC_DIM, nullptr, lg, KCLS, B_ROWS, KCLS, ENC_DIM, false);
    // argmax / y / z_q gather (also fills g_cat cols [1024,1080))
    argmax_y_kernel<<<B_ROWS, 32>>>(lg, mask, labels, codebook, zq);
    // VAE encoder
    launch_gemm(x, IN_DIM, W1, IN_DIM, b1, p_h, VDIM, B_ROWS, VDIM, IN_DIM, true);
    launch_gemm(p_h, VDIM, W2, VDIM, b2, p_ml, 2 * VDIM, B_ROWS, 2 * VDIM, VDIM, false);
    // reparam + KL
    vae_post_kernel<<<B_ROWS, 256>>>(eps);
    kl_reduce_kernel<<<1, 256>>>(kl);
    // decoder
    launch_gemm(p_cat, CAT_LD, p_wd, CAT_LD, bd, xt, IN_DIM, B_ROWS, IN_DIM, CAT_LD, false);
}

// round 3
// speedup vs baseline: 1.0023x; 1.0023x over previous
#include <cuda_runtime.h>
#include <math.h>

// ---------------- problem constants ----------------
#define B_ROWS 16384
#define IN_DIM 768
#define ENC_DIM 500
#define KCLS 43
#define VDIM 1024
#define CAT_RAW 1067          // VDIM + KCLS
#define CAT_LD  1080          // padded, multiple of 8 floats (16B aligned rows)

// ---------------- scratch (static device globals: no allocation) ----------------
__device__ float g_h  [(size_t)B_ROWS * VDIM];        // relu(x@W1^T)
__device__ float g_ml [(size_t)B_ROWS * 2 * VDIM];    // mu||logvar
__device__ float g_cat[(size_t)B_ROWS * CAT_LD];      // [sampled_z | y | 0pad]
__device__ float g_Wd [(size_t)IN_DIM * CAT_LD];      // padded decoder weight
__device__ float g_klp[B_ROWS];                        // per-row KL partials
__device__ float g_ze_s[(size_t)B_ROWS * ENC_DIM];     // fallback scratch
__device__ float g_zq_s[(size_t)B_ROWS * ENC_DIM];
__device__ float g_lg_s[(size_t)B_ROWS * KCLS];
__device__ float g_kl_s[1];
__device__ int   g_mask_mode;                          // 0=bool bytes,1=int32,2=float32

// ---------------- generic TN SGEMM: C[M,N] = A[M,K] @ B[N,K]^T (+bias)(+relu) ----------------
#define BM 128
#define BN 128
#define BK 16

template<bool RELU>
__global__ __launch_bounds__(256, 2)
void sgemm_tn(const float* __restrict__ A, int lda,
              const float* __restrict__ Bm, int ldb,
              const float* __restrict__ bias,
              float* __restrict__ C, int ldc,
              int M, int N, int K)
{
    __shared__ float As[BK][BM];
    __shared__ float Bs[BK][BN];

    const int tid = threadIdx.x;
    const int m0 = blockIdx.y * BM;
    const int n0 = blockIdx.x * BN;
    const int tx = tid & 15;
    const int ty = tid >> 4;

    float acc[8][8];
#pragma unroll
    for (int i = 0; i < 8; i++)
#pragma unroll
        for (int j = 0; j < 8; j++) acc[i][j] = 0.f;

    const int lrow = tid >> 2;        // 0..63 (two halves: +0, +64)
    const int lkq  = (tid & 3) * 4;   // 0,4,8,12

    for (int k0 = 0; k0 < K; k0 += BK) {
        // ---- load A tile (transposed into As[k][m]) ----
#pragma unroll
        for (int h = 0; h < 2; h++) {
            int row = lrow + h * 64;
            int gr = m0 + row;
            int kk = k0 + lkq;
            float4 v = make_float4(0.f, 0.f, 0.f, 0.f);
            if (gr < M) {
                const float* p = A + (size_t)gr * lda + kk;
                if (kk + 3 < K) v = *reinterpret_cast<const float4*>(p);
                else {
                    if (kk + 0 < K) v.x = p[0];
                    if (kk + 1 < K) v.y = p[1];
                    if (kk + 2 < K) v.z = p[2];
                    if (kk + 3 < K) v.w = p[3];
                }
            }
            As[lkq + 0][row] = v.x;
            As[lkq + 1][row] = v.y;
            As[lkq + 2][row] = v.z;
            As[lkq + 3][row] = v.w;
        }
        // ---- load B tile ----
#pragma unroll
        for (int h = 0; h < 2; h++) {
            int row = lrow + h * 64;
            int gr = n0 + row;
            int kk = k0 + lkq;
            float4 v = make_float4(0.f, 0.f, 0.f, 0.f);
            if (gr < N) {
                const float* p = Bm + (size_t)gr * ldb + kk;
                if (kk + 3 < K) v = *reinterpret_cast<const float4*>(p);
                else {
                    if (kk + 0 < K) v.x = p[0];
                    if (kk + 1 < K) v.y = p[1];
                    if (kk + 2 < K) v.z = p[2];
                    if (kk + 3 < K) v.w = p[3];
                }
            }
            Bs[lkq + 0][row] = v.x;
            Bs[lkq + 1][row] = v.y;
            Bs[lkq + 2][row] = v.z;
            Bs[lkq + 3][row] = v.w;
        }
        __syncthreads();

#pragma unroll
        for (int k = 0; k < BK; k++) {
            float4 a0 = *reinterpret_cast<const float4*>(&As[k][ty * 4]);
            float4 a1 = *reinterpret_cast<const float4*>(&As[k][64 + ty * 4]);
            float4 b0 = *reinterpret_cast<const float4*>(&Bs[k][tx * 4]);
            float4 b1 = *reinterpret_cast<const float4*>(&Bs[k][64 + tx * 4]);
            float a[8] = {a0.x, a0.y, a0.z, a0.w, a1.x, a1.y, a1.z, a1.w};
            float b[8] = {b0.x, b0.y, b0.z, b0.w, b1.x, b1.y, b1.z, b1.w};
#pragma unroll
            for (int i = 0; i < 8; i++)
#pragma unroll
                for (int j = 0; j < 8; j++)
                    acc[i][j] = fmaf(a[i], b[j], acc[i][j]);
        }
        __syncthreads();
    }

    // ---- epilogue ----
#pragma unroll
    for (int i = 0; i < 8; i++) {
        int row = m0 + ((i < 4) ? (ty * 4 + i) : (64 + ty * 4 + i - 4));
        if (row >= M) continue;
#pragma unroll
        for (int j = 0; j < 8; j++) {
            int col = n0 + ((j < 4) ? (tx * 4 + j) : (64 + tx * 4 + j - 4));
            if (col < N) {
                float v = acc[i][j];
                if (bias) v += bias[col];
                if (RELU) v = fmaxf(v, 0.f);
                C[(size_t)row * ldc + col] = v;
            }
        }
    }
}

// ---------------- pack Wd (768 x 1067) into padded (768 x 1080) ----------------
__global__ void pack_wd_kernel(const float* __restrict__ Wd)
{
    int idx = blockIdx.x * blockDim.x + threadIdx.x;
    const int total = IN_DIM * CAT_LD;
    if (idx >= total) return;
    int r = idx / CAT_LD;
    int c = idx - r * CAT_LD;
    g_Wd[idx] = (c < CAT_RAW) ? Wd[(size_t)r * CAT_RAW + c] : 0.f;
}

// ---------------- detect known_mask dtype (bool bytes vs int32 vs float32) ----------------
__global__ void detect_mask_kernel(const unsigned int* __restrict__ w)
{
    __shared__ int s_int, s_flt;
    if (threadIdx.x == 0) { s_int = 1; s_flt = 1; }
    __syncthreads();
    int li = 1, lf = 1;
    // 4096 words = 16KB, valid under every dtype interpretation of 16384 elements
    for (int i = threadIdx.x; i < 4096; i += blockDim.x) {
        unsigned v = w[i];
        if (v > 1u) li = 0;
        if (v != 0u && v != 0x3F800000u) lf = 0;
    }
    if (!li) atomicAnd(&s_int, 0);
    if (!lf) atomicAnd(&s_flt, 0);
    __syncthreads();
    if (threadIdx.x == 0) g_mask_mode = s_int ? 1 : (s_flt ? 2 : 0);
}

// ---------------- argmax + softmax(y) + codebook gather; one warp per row ----------------
__global__ void argmax_y_kernel(const float* __restrict__ logits,
                                const void*  __restrict__ mask,
                                const int*   __restrict__ labels,
                                const float* __restrict__ codebook,
                                float* __restrict__ zq)
{
    const int b = blockIdx.x;
    const int lane = threadIdx.x;
    const float NEG_INF = __int_as_float(0xff800000u);

    const float* lr = logits + (size_t)b * KCLS;
    float v0 = (lane < KCLS) ? lr[lane] : NEG_INF;
    float v1 = (lane + 32 < KCLS) ? lr[lane + 32] : NEG_INF;

    float m; int mi;
    if (v0 >= v1) { m = v0; mi = lane; } else { m = v1; mi = lane + 32; }
#pragma unroll
    for (int off = 16; off > 0; off >>= 1) {
        float om = __shfl_xor_sync(0xffffffffu, m, off);
        int   oi = __shfl_xor_sync(0xffffffffu, mi, off);
        if (om > m || (om == m && oi < mi)) { m = om; mi = oi; }
    }

    float e0 = (lane < KCLS) ? expf(v0 - m) : 0.f;
    float e1 = (lane + 32 < KCLS) ? expf(v1 - m) : 0.f;
    float s = e0 + e1;
#pragma unroll
    for (int off = 16; off > 0; off >>= 1)
        s += __shfl_xor_sync(0xffffffffu, s, off);
    float inv = 1.0f / s;

    int mode = g_mask_mode;
    bool known;
    if (mode == 1)      known = ((const int*)mask)[b] != 0;
    else if (mode == 2) known = ((const float*)mask)[b] != 0.f;
    else                known = ((const unsigned char*)mask)[b] != 0;
    int lab = labels[b];

    float* yr = g_cat + (size_t)b * CAT_LD + VDIM;   // 56 slots (43 real + pad)
    {
        int k = lane;
        float val = (k < KCLS) ? (known ? (k == lab ? 1.f : 0.f) : e0 * inv) : 0.f;
        yr[k] = val;
        k = lane + 32;
        if (k < CAT_LD - VDIM) {
            float val2 = (k < KCLS) ? (known ? (k == lab ? 1.f : 0.f) : e1 * inv) : 0.f;
            yr[k] = val2;
        }
    }

    const float* cr = codebook + (size_t)mi * ENC_DIM;
    float* zr = zq + (size_t)b * ENC_DIM;
    for (int i = lane; i < ENC_DIM; i += 32) zr[i] = cr[i];
}

// ---------------- reparam sample + per-row KL partial ----------------
__global__ void vae_post_kernel(const float* __restrict__ eps)
{
    const int b = blockIdx.x;
    const int t = threadIdx.x;
    const float* mlr = g_ml + (size_t)b * (2 * VDIM);
    const float* er  = eps + (size_t)b * VDIM;
    float* zr = g_cat + (size_t)b * CAT_LD;

    float kl = 0.f;
    for (int i = t; i < VDIM; i += 256) {
        float mu = mlr[i];
        float lv = mlr[VDIM + i];
        float elv = expf(lv);
        kl += 0.5f * (elv + mu * mu - 1.0f - lv);
        zr[i] = fmaf(expf(0.5f * lv), er[i], mu);
    }
    __shared__ float sm[256];
    sm[t] = kl;
    __syncthreads();
    for (int st = 128; st > 0; st >>= 1) {
        if (t < st) sm[t] += sm[t + st];
        __syncthreads();
    }
    if (t == 0) g_klp[b] = sm[0];
}

// ---------------- deterministic final KL reduction ----------------
__global__ void kl_reduce_kernel(float* __restrict__ out)
{
    const int t = threadIdx.x;
    float s = 0.f;
    for (int i = t; i < B_ROWS; i += 256) s += g_klp[i];
    __shared__ float sm[256];
    sm[t] = s;
    __syncthreads();
    for (int st = 128; st > 0; st >>= 1) {
        if (t < st) sm[t] += sm[t + st];
        __syncthreads();
    }
    if (t == 0) *out = sm[0] / (float)B_ROWS;
}

// ---------------- host-side GEMM launcher ----------------
static void launch_gemm(const float* A, int lda, const float* Bm, int ldb,
                        const float* bias, float* C, int ldc,
                        int M, int N, int K, bool relu)
{
    dim3 grid((N + BN - 1) / BN, (M + BM - 1) / BM);
    if (relu) sgemm_tn<true ><<<grid, 256>>>(A, lda, Bm, ldb, bias, C, ldc, M, N, K);
    else      sgemm_tn<false><<<grid, 256>>>(A, lda, Bm, ldb, bias, C, ldc, M, N, K);
}

extern "C" void kernel_launch(void* const* d_in, const int* in_sizes, int n_in,
                              void* d_out, int out_size)
{
    const float* x        = (const float*)d_in[0];
    const void*  mask     = d_in[1];
    const int*   labels   = (const int*)d_in[2];
    const float* eps      = (const float*)d_in[3];
    const float* W_enc    = (const float*)d_in[4];
    const float* b_enc    = (const float*)d_in[5];
    const float* codebook = (const float*)d_in[6];
    const float* W1       = (const float*)d_in[7];
    const float* b1       = (const float*)d_in[8];
    const float* W2       = (const float*)d_in[9];
    const float* b2       = (const float*)d_in[10];
    const float* Wd       = (const float*)d_in[11];
    const float* bd       = (const float*)d_in[12];

    float* out = (float*)d_out;

    // scratch symbol addresses (query each call; capture-safe, non-stream API)
    float *p_h, *p_ml, *p_cat, *p_wd, *p_ze_s, *p_zq_s, *p_lg_s, *p_kl_s;
    cudaGetSymbolAddress((void**)&p_h,    g_h);
    cudaGetSymbolAddress((void**)&p_ml,   g_ml);
    cudaGetSymbolAddress((void**)&p_cat,  g_cat);
    cudaGetSymbolAddress((void**)&p_wd,   g_Wd);
    cudaGetSymbolAddress((void**)&p_ze_s, g_ze_s);
    cudaGetSymbolAddress((void**)&p_zq_s, g_zq_s);
    cudaGetSymbolAddress((void**)&p_lg_s, g_lg_s);
    cudaGetSymbolAddress((void**)&p_kl_s, g_kl_s);

    // output layout: tuple (x_tilde, z_e_x, z_q_x, logits, kl_div) flattened.
    const size_t full_elems = (size_t)B_ROWS * (IN_DIM + ENC_DIM + ENC_DIM + KCLS) + 1;
    const bool full = ((size_t)out_size >= full_elems);
    float* xt = out;
    float* ze = full ? out + (size_t)B_ROWS * IN_DIM : p_ze_s;
    float* zq = full ? ze + (size_t)B_ROWS * ENC_DIM : p_zq_s;
    float* lg = full ? zq + (size_t)B_ROWS * ENC_DIM : p_lg_s;
    float* kl = full ? lg + (size_t)B_ROWS * KCLS    : p_kl_s;

    // independent prep
    pack_wd_kernel<<<(IN_DIM * CAT_LD + 255) / 256, 256>>>(Wd);
    detect_mask_kernel<<<1, 256>>>((const unsigned int*)mask);

    // encoder
    launch_gemm(x, IN_DIM, W_enc, IN_DIM, b_enc, ze, ENC_DIM, B_ROWS, ENC_DIM, IN_DIM, false);
    // logits
    launch_gemm(ze, ENC_DIM, codebook, ENC_DIM, nullptr, lg, KCLS, B_ROWS, KCLS, ENC_DIM, false);
    // argmax / y / z_q gather (also fills g_cat cols [1024,1080))
    argmax_y_kernel<<<B_ROWS, 32>>>(lg, mask, labels, codebook, zq);
    // VAE encoder
    launch_gemm(x, IN_DIM, W1, IN_DIM, b1, p_h, VDIM, B_ROWS, VDIM, IN_DIM, true);
    launch_gemm(p_h, VDIM, W2, VDIM, b2, p_ml, 2 * VDIM, B_ROWS, 2 * VDIM, VDIM, false);
    // reparam + KL
    vae_post_kernel<<<B_ROWS, 256>>>(eps);
    kl_reduce_kernel<<<1, 256>>>(kl);
    // decoder
    launch_gemm(p_cat, CAT_LD, p_wd, CAT_LD, bd, xt, IN_DIM, B_ROWS, IN_DIM, CAT_LD, false);
}

// round 5
// speedup vs baseline: 1.8767x; 1.8725x over previous
#include <cuda_runtime.h>
#include <cuda_bf16.h>
#include <math.h>
#include <stdint.h>

#define B_ROWS 16384
#define IN_DIM 768
#define ENC_DIM 500
#define KCLS 43
#define VDIM 1024
#define CAT_RAW 1067
#define CAT_LD  1088   // multiple of 64

// ---------------- scratch ----------------
__device__ float g_h  [(size_t)B_ROWS * VDIM];
__device__ float g_ml [(size_t)B_ROWS * 2 * VDIM];
__device__ float g_cat[(size_t)B_ROWS * CAT_LD];
__device__ float g_Wd [(size_t)IN_DIM * CAT_LD];
__device__ float g_G  [(size_t)KCLS * IN_DIM];
__device__ float g_lb [KCLS];
__device__ float g_klp[B_ROWS];
__device__ float g_ze_s[(size_t)B_ROWS * ENC_DIM];
__device__ float g_zq_s[(size_t)B_ROWS * ENC_DIM];
__device__ float g_lg_s[(size_t)B_ROWS * KCLS];
__device__ float g_kl_s[1];
__device__ int   g_mask_mode;

// ---------------- helpers ----------------
__device__ __forceinline__ uint32_t smem_to_u32(const void* p) {
    uint32_t a;
    asm("{ .reg .u64 t; cvta.to.shared.u64 t, %1; cvt.u32.u64 %0, t; }" : "=r"(a) : "l"(p));
    return a;
}
#define SWZ(b) ((b) ^ (((b) >> 3) & 0x70))

__device__ __forceinline__ void ldsm_x4(uint32_t* r, uint32_t addr) {
    asm volatile("ldmatrix.sync.aligned.m8n8.x4.shared.b16 {%0,%1,%2,%3}, [%4];"
        : "=r"(r[0]), "=r"(r[1]), "=r"(r[2]), "=r"(r[3]) : "r"(addr));
}
__device__ __forceinline__ void mma16816(float* c, const uint32_t* a, const uint32_t* b) {
    asm volatile("mma.sync.aligned.m16n8k16.row.col.f32.bf16.bf16.f32 "
        "{%0,%1,%2,%3}, {%4,%5,%6,%7}, {%8,%9}, {%0,%1,%2,%3};"
        : "+f"(c[0]), "+f"(c[1]), "+f"(c[2]), "+f"(c[3])
        : "r"(a[0]), "r"(a[1]), "r"(a[2]), "r"(a[3]), "r"(b[0]), "r"(b[1]));
}

// split fp32 -> hi (truncate to bf16) + lo (rn bf16 of remainder)
__device__ __forceinline__ void split_store(char* hi, char* lo, uint32_t off, float4 v) {
    uint32_t ux = __float_as_uint(v.x), uy = __float_as_uint(v.y);
    uint32_t uz = __float_as_uint(v.z), uw = __float_as_uint(v.w);
    uint2 H, L;
    H.x = __byte_perm(ux, uy, 0x7632);
    H.y = __byte_perm(uz, uw, 0x7632);
    float lx = v.x - __uint_as_float(ux & 0xFFFF0000u);
    float ly = v.y - __uint_as_float(uy & 0xFFFF0000u);
    float lz = v.z - __uint_as_float(uz & 0xFFFF0000u);
    float lw = v.w - __uint_as_float(uw & 0xFFFF0000u);
    asm("cvt.rn.bf16x2.f32 %0, %1, %2;" : "=r"(L.x) : "f"(ly), "f"(lx));
    asm("cvt.rn.bf16x2.f32 %0, %1, %2;" : "=r"(L.y) : "f"(lw), "f"(lz));
    *reinterpret_cast<uint2*>(hi + off) = H;
    *reinterpret_cast<uint2*>(lo + off) = L;
}

// ---------------- mma.sync bf16x3 GEMM: C[M,N] = A[M,K] @ B[N,K]^T + bias ----------------
// CTA 128x128, 8 warps (2x4), warp tile 64x32, K chunk 64.
// SMEM: Ah(16K) Al(16K) Bh(16K) Bl(16K) = 64KB, 1024-aligned.
#define TILE_AH 0u
#define TILE_AL 16384u
#define TILE_BH 32768u
#define TILE_BL 49152u
#define GEMM_DYN (65536 + 1024)

__global__ __launch_bounds__(256, 2)
void gemm_mma(const float* __restrict__ A, int lda,
              const float* __restrict__ Bw, int ldb, int nB,
              const float* __restrict__ bias,
              float* __restrict__ C, int ldc, int nOut,
              int K, int relu)
{
    extern __shared__ char smem[];
    const uint32_t sbase = smem_to_u32(smem);
    const uint32_t tiles = (sbase + 1023) & ~1023u;
    char* tp = smem + (tiles - sbase);

    const int tid = threadIdx.x;
    const int wid = tid >> 5;
    const int lane = tid & 31;
    const int m0 = blockIdx.y * 128;
    const int n0 = blockIdx.x * 128;
    const int wm = (wid >> 2) * 64;   // warp row: 0 or 64
    const int wn = (wid & 3) * 32;    // warp col: 0/32/64/96

    float acc[4][4][4];
#pragma unroll
    for (int i = 0; i < 4; i++)
#pragma unroll
        for (int j = 0; j < 4; j++)
#pragma unroll
            for (int q = 0; q < 4; q++) acc[i][j][q] = 0.f;

    // ldmatrix lane address components
    const uint32_t aRowByte = (uint32_t)(wm + (lane & 15)) * 128u;
    const uint32_t aKoff    = (uint32_t)((lane >> 4) * 16);           // bytes
    const uint32_t bRowByte = (uint32_t)(wn + (lane & 7) + ((lane >> 4) << 3)) * 128u;
    const uint32_t bKoff    = (uint32_t)(((lane >> 3) & 1) * 16);     // bytes

    const int S = K / 64;
    for (int s = 0; s < S; s++) {
        const int k0 = s * 64;
        // ---- load + split A and B tiles (128 x 64 f32 each) ----
#pragma unroll
        for (int i = 0; i < 8; i++) {
            int idx = i * 256 + tid;
            int row = idx >> 4, c4 = idx & 15;
            uint32_t off = SWZ((uint32_t)(row * 128 + c4 * 8));
            float4 va = *reinterpret_cast<const float4*>(A + (size_t)(m0 + row) * lda + k0 + c4 * 4);
            split_store(tp + TILE_AH, tp + TILE_AL, off, va);
            float4 vb = make_float4(0.f, 0.f, 0.f, 0.f);
            int gr = n0 + row;
            if (gr < nB) vb = *reinterpret_cast<const float4*>(Bw + (size_t)gr * ldb + k0 + c4 * 4);
            split_store(tp + TILE_BH, tp + TILE_BL, off, vb);
        }
        __syncthreads();

        // ---- 3 passes: Ah*Bh, Al*Bh, Ah*Bl ----
#pragma unroll
        for (int pass = 0; pass < 3; pass++) {
            const uint32_t pa = tiles + ((pass == 1) ? TILE_AL : TILE_AH);
            const uint32_t pb = tiles + ((pass == 2) ? TILE_BL : TILE_BH);
#pragma unroll
            for (int kk = 0; kk < 4; kk++) {
                const uint32_t kb = (uint32_t)(kk * 32);   // 16 elems * 2B
                uint32_t a[4][4], b[2][4];
#pragma unroll
                for (int mt = 0; mt < 4; mt++)
                    ldsm_x4(a[mt], pa + SWZ(aRowByte + (uint32_t)(mt * 2048) + kb + aKoff));
#pragma unroll
                for (int nb = 0; nb < 2; nb++)
                    ldsm_x4(b[nb], pb + SWZ(bRowByte + (uint32_t)(nb * 2048) + kb + bKoff));
#pragma unroll
                for (int mt = 0; mt < 4; mt++)
#pragma unroll
                    for (int nt = 0; nt < 4; nt++)
                        mma16816(acc[mt][nt], a[mt], &b[nt >> 1][(nt & 1) * 2]);
            }
        }
        __syncthreads();
    }

    // ---- epilogue: bias (+relu), float2 stores ----
#pragma unroll
    for (int mt = 0; mt < 4; mt++) {
        const int r0 = m0 + wm + mt * 16 + (lane >> 2);
        float* crow0 = C + (size_t)r0 * ldc;
        float* crow8 = C + (size_t)(r0 + 8) * ldc;
#pragma unroll
        for (int nt = 0; nt < 4; nt++) {
            const int c = n0 + wn + nt * 8 + (lane & 3) * 2;
            if (c >= nOut) continue;
            float b0 = bias[c], b1 = bias[c + 1];
            float v0 = acc[mt][nt][0] + b0, v1 = acc[mt][nt][1] + b1;
            float v2 = acc[mt][nt][2] + b0, v3 = acc[mt][nt][3] + b1;
            if (relu) {
                v0 = fmaxf(v0, 0.f); v1 = fmaxf(v1, 0.f);
                v2 = fmaxf(v2, 0.f); v3 = fmaxf(v3, 0.f);
            }
            *reinterpret_cast<float2*>(crow0 + c) = make_float2(v0, v1);
            *reinterpret_cast<float2*>(crow8 + c) = make_float2(v2, v3);
        }
    }
}

// ---------------- fp32 SGEMM (logits only): C = A @ B^T + bias ----------------
#define BM 128
#define BN 128
#define BK 16
__global__ __launch_bounds__(256, 2)
void sgemm_tn(const float* __restrict__ A, int lda,
              const float* __restrict__ Bm, int ldb,
              const float* __restrict__ bias,
              float* __restrict__ C, int ldc, int M, int N, int K)
{
    __shared__ float As[BK][BM];
    __shared__ float Bs[BK][BN];
    const int tid = threadIdx.x;
    const int m0 = blockIdx.y * BM, n0 = blockIdx.x * BN;
    const int tx = tid & 15, ty = tid >> 4;
    float acc[8][8];
#pragma unroll
    for (int i = 0; i < 8; i++)
#pragma unroll
        for (int j = 0; j < 8; j++) acc[i][j] = 0.f;
    const int lrow = tid >> 2, lkq = (tid & 3) * 4;
    for (int k0 = 0; k0 < K; k0 += BK) {
#pragma unroll
        for (int h = 0; h < 2; h++) {
            int row = lrow + h * 64, gr = m0 + row, kk = k0 + lkq;
            float4 v = make_float4(0.f, 0.f, 0.f, 0.f);
            if (gr < M) v = *reinterpret_cast<const float4*>(A + (size_t)gr * lda + kk);
            As[lkq + 0][row] = v.x; As[lkq + 1][row] = v.y;
            As[lkq + 2][row] = v.z; As[lkq + 3][row] = v.w;
        }
#pragma unroll
        for (int h = 0; h < 2; h++) {
            int row = lrow + h * 64, gr = n0 + row, kk = k0 + lkq;
            float4 v = make_float4(0.f, 0.f, 0.f, 0.f);
            if (gr < N) v = *reinterpret_cast<const float4*>(Bm + (size_t)gr * ldb + kk);
            Bs[lkq + 0][row] = v.x; Bs[lkq + 1][row] = v.y;
            Bs[lkq + 2][row] = v.z; Bs[lkq + 3][row] = v.w;
        }
        __syncthreads();
#pragma unroll
        for (int k = 0; k < BK; k++) {
            float4 a0 = *reinterpret_cast<const float4*>(&As[k][ty * 4]);
            float4 a1 = *reinterpret_cast<const float4*>(&As[k][64 + ty * 4]);
            float4 b0 = *reinterpret_cast<const float4*>(&Bs[k][tx * 4]);
            float4 b1 = *reinterpret_cast<const float4*>(&Bs[k][64 + tx * 4]);
            float a[8] = {a0.x, a0.y, a0.z, a0.w, a1.x, a1.y, a1.z, a1.w};
            float b[8] = {b0.x, b0.y, b0.z, b0.w, b1.x, b1.y, b1.z, b1.w};
#pragma unroll
            for (int i = 0; i < 8; i++)
#pragma unroll
                for (int j = 0; j < 8; j++)
                    acc[i][j] = fmaf(a[i], b[j], acc[i][j]);
        }
        __syncthreads();
    }
#pragma unroll
    for (int i = 0; i < 8; i++) {
        int row = m0 + ((i < 4) ? (ty * 4 + i) : (64 + ty * 4 + i - 4));
        if (row >= M) continue;
#pragma unroll
        for (int j = 0; j < 8; j++) {
            int col = n0 + ((j < 4) ? (tx * 4 + j) : (64 + tx * 4 + j - 4));
            if (col < N) C[(size_t)row * ldc + col] = acc[i][j] + bias[col];
        }
    }
}

// ---------------- prep kernels ----------------
__global__ void pack_wd_kernel(const float* __restrict__ Wd)
{
    int idx = blockIdx.x * blockDim.x + threadIdx.x;
    if (idx >= IN_DIM * CAT_LD) return;
    int r = idx / CAT_LD, c = idx - r * CAT_LD;
    g_Wd[idx] = (c < CAT_RAW) ? Wd[(size_t)r * CAT_RAW + c] : 0.f;
}

// G[c][i] = sum_d codebook[c][d] * W_enc[d][i]
__global__ void build_G(const float* __restrict__ W_enc, const float* __restrict__ cb)
{
    int c = blockIdx.x;
    int i = blockIdx.y * 128 + threadIdx.x;
    float s = 0.f;
    for (int d = 0; d < ENC_DIM; d++)
        s = fmaf(cb[c * ENC_DIM + d], W_enc[(size_t)d * IN_DIM + i], s);
    g_G[(size_t)c * IN_DIM + i] = s;
}
__global__ void build_lb(const float* __restrict__ b_enc, const float* __restrict__ cb)
{
    int c = threadIdx.x;
    if (c >= KCLS) return;
    float s = 0.f;
    for (int d = 0; d < ENC_DIM; d++) s = fmaf(b_enc[d], cb[c * ENC_DIM + d], s);
    g_lb[c] = s;
}

__global__ void detect_mask_kernel(const unsigned int* __restrict__ w)
{
    __shared__ int s_int, s_flt;
    if (threadIdx.x == 0) { s_int = 1; s_flt = 1; }
    __syncthreads();
    int li = 1, lf = 1;
    for (int i = threadIdx.x; i < 4096; i += blockDim.x) {
        unsigned v = w[i];
        if (v > 1u) li = 0;
        if (v != 0u && v != 0x3F800000u) lf = 0;
    }
    if (!li) atomicAnd(&s_int, 0);
    if (!lf) atomicAnd(&s_flt, 0);
    __syncthreads();
    if (threadIdx.x == 0) g_mask_mode = s_int ? 1 : (s_flt ? 2 : 0);
}

__global__ void argmax_y_kernel(const float* __restrict__ logits,
                                const void* __restrict__ mask,
                                const int* __restrict__ labels,
                                const float* __restrict__ codebook,
                                float* __restrict__ zq)
{
    const int b = blockIdx.x;
    const int lane = threadIdx.x;
    const float NEG = __int_as_float(0xff800000u);
    const float* lr = logits + (size_t)b * KCLS;
    float v0 = (lane < KCLS) ? lr[lane] : NEG;
    float v1 = (lane + 32 < KCLS) ? lr[lane + 32] : NEG;
    float m; int mi;
    if (v0 >= v1) { m = v0; mi = lane; } else { m = v1; mi = lane + 32; }
#pragma unroll
    for (int off = 16; off > 0; off >>= 1) {
        float om = __shfl_xor_sync(0xffffffffu, m, off);
        int oi = __shfl_xor_sync(0xffffffffu, mi, off);
        if (om > m || (om == m && oi < mi)) { m = om; mi = oi; }
    }
    float e0 = (lane < KCLS) ? expf(v0 - m) : 0.f;
    float e1 = (lane + 32 < KCLS) ? expf(v1 - m) : 0.f;
    float s = e0 + e1;
#pragma unroll
    for (int off = 16; off > 0; off >>= 1) s += __shfl_xor_sync(0xffffffffu, s, off);
    float inv = 1.0f / s;

    int mode = g_mask_mode;
    bool known;
    if (mode == 1)      known = ((const int*)mask)[b] != 0;
    else if (mode == 2) known = ((const float*)mask)[b] != 0.f;
    else                known = ((const unsigned char*)mask)[b] != 0;
    int lab = labels[b];

    float* yr = g_cat + (size_t)b * CAT_LD + VDIM;   // 64 slots (43 real + pad)
    yr[lane] = (lane < KCLS) ? (known ? (lane == lab ? 1.f : 0.f) : e0 * inv) : 0.f;
    yr[lane + 32] = (lane + 32 < KCLS) ? (known ? (lane + 32 == lab ? 1.f : 0.f) : e1 * inv) : 0.f;

    const float* cr = codebook + (size_t)mi * ENC_DIM;
    float* zr = zq + (size_t)b * ENC_DIM;
    for (int i = lane; i < ENC_DIM; i += 32) zr[i] = cr[i];
}

__global__ void vae_post_kernel(const float* __restrict__ eps)
{
    const int b = blockIdx.x;
    const int t = threadIdx.x;
    const float* mlr = g_ml + (size_t)b * (2 * VDIM);
    const float* er = eps + (size_t)b * VDIM;
    float* zr = g_cat + (size_t)b * CAT_LD;
    float kl = 0.f;
    for (int i = t; i < VDIM; i += 256) {
        float mu = mlr[i], lv = mlr[VDIM + i];
        kl += 0.5f * (expf(lv) + mu * mu - 1.0f - lv);
        zr[i] = fmaf(expf(0.5f * lv), er[i], mu);
    }
    __shared__ float sm[256];
    sm[t] = kl;
    __syncthreads();
    for (int st = 128; st > 0; st >>= 1) { if (t < st) sm[t] += sm[t + st]; __syncthreads(); }
    if (t == 0) g_klp[b] = sm[0];
}

__global__ void kl_reduce_kernel(float* __restrict__ out)
{
    const int t = threadIdx.x;
    float s = 0.f;
    for (int i = t; i < B_ROWS; i += 256) s += g_klp[i];
    __shared__ float sm[256];
    sm[t] = s;
    __syncthreads();
    for (int st = 128; st > 0; st >>= 1) { if (t < st) sm[t] += sm[t + st]; __syncthreads(); }
    if (t == 0) *out = sm[0] / (float)B_ROWS;
}

// ---------------- host ----------------
static void launch_tc(const float* A, int lda, const float* Bw, int ldb, int nB,
                      const float* bias, float* C, int ldc, int nOut, int K, int relu)
{
    static int attr_set = 0;
    if (!attr_set) {
        cudaFuncSetAttribute(gemm_mma, cudaFuncAttributeMaxDynamicSharedMemorySize, GEMM_DYN);
        attr_set = 1;
    }
    dim3 grid((nOut + 127) / 128, B_ROWS / 128);
    gemm_mma<<<grid, 256, GEMM_DYN>>>(A, lda, Bw, ldb, nB, bias, C, ldc, nOut, K, relu);
}

extern "C" void kernel_launch(void* const* d_in, const int* in_sizes, int n_in,
                              void* d_out, int out_size)
{
    const float* x        = (const float*)d_in[0];
    const void*  mask     = d_in[1];
    const int*   labels   = (const int*)d_in[2];
    const float* eps      = (const float*)d_in[3];
    const float* W_enc    = (const float*)d_in[4];
    const float* b_enc    = (const float*)d_in[5];
    const float* codebook = (const float*)d_in[6];
    const float* W1       = (const float*)d_in[7];
    const float* b1       = (const float*)d_in[8];
    const float* W2       = (const float*)d_in[9];
    const float* b2       = (const float*)d_in[10];
    const float* Wd       = (const float*)d_in[11];
    const float* bd       = (const float*)d_in[12];
    float* out = (float*)d_out;

    float *p_h, *p_ml, *p_cat, *p_wd, *p_G, *p_lb, *p_ze, *p_zq, *p_lg, *p_kl;
    cudaGetSymbolAddress((void**)&p_h,  g_h);
    cudaGetSymbolAddress((void**)&p_ml, g_ml);
    cudaGetSymbolAddress((void**)&p_cat, g_cat);
    cudaGetSymbolAddress((void**)&p_wd, g_Wd);
    cudaGetSymbolAddress((void**)&p_G,  g_G);
    cudaGetSymbolAddress((void**)&p_lb, g_lb);
    cudaGetSymbolAddress((void**)&p_ze, g_ze_s);
    cudaGetSymbolAddress((void**)&p_zq, g_zq_s);
    cudaGetSymbolAddress((void**)&p_lg, g_lg_s);
    cudaGetSymbolAddress((void**)&p_kl, g_kl_s);

    const size_t full_elems = (size_t)B_ROWS * (IN_DIM + ENC_DIM + ENC_DIM + KCLS) + 1;
    const bool full = ((size_t)out_size >= full_elems);
    float* xt = out;
    float* ze = full ? out + (size_t)B_ROWS * IN_DIM : p_ze;
    float* zq = full ? ze + (size_t)B_ROWS * ENC_DIM : p_zq;
    float* lg = full ? zq + (size_t)B_ROWS * ENC_DIM : p_lg;
    float* kl = full ? lg + (size_t)B_ROWS * KCLS    : p_kl;

    // prep (independent)
    pack_wd_kernel<<<(IN_DIM * CAT_LD + 255) / 256, 256>>>(Wd);
    detect_mask_kernel<<<1, 256>>>((const unsigned int*)mask);
    build_G<<<dim3(KCLS, IN_DIM / 128), 128>>>(W_enc, codebook);
    build_lb<<<1, 64>>>(b_enc, codebook);

    // z_e_x (tensor cores, bf16x3)
    launch_tc(x, IN_DIM, W_enc, IN_DIM, ENC_DIM, b_enc, ze, ENC_DIM, ENC_DIM, IN_DIM, 0);
    // logits (exact fp32 via G = codebook @ W_enc)
    {
        dim3 grid((KCLS + BN - 1) / BN, (B_ROWS + BM - 1) / BM);
        sgemm_tn<<<grid, 256>>>(x, IN_DIM, p_G, IN_DIM, p_lb, lg, KCLS, B_ROWS, KCLS, IN_DIM);
    }
    argmax_y_kernel<<<B_ROWS, 32>>>(lg, mask, labels, codebook, zq);
    // VAE encoder
    launch_tc(x, IN_DIM, W1, IN_DIM, VDIM, b1, p_h, VDIM, VDIM, IN_DIM, 1);
    launch_tc(p_h, VDIM, W2, VDIM, 2 * VDIM, b2, p_ml, 2 * VDIM, 2 * VDIM, VDIM, 0);
    vae_post_kernel<<<B_ROWS, 256>>>(eps);
    kl_reduce_kernel<<<1, 256>>>(kl);
    // decoder
    launch_tc(p_cat, CAT_LD, p_wd, CAT_LD, IN_DIM, bd, xt, IN_DIM, IN_DIM, CAT_LD, 0);
}

// round 6
// speedup vs baseline: 2.7972x; 1.4905x over previous
#include <cuda_runtime.h>
#include <cuda_bf16.h>
#include <math.h>
#include <stdint.h>

#define B_ROWS 16384
#define IN_DIM 768
#define ENC_DIM 500
#define ZE_NPAD 512
#define KCLS 43
#define VDIM 1024
#define CAT_RAW 1067
#define CAT_LD  1088   // multiple of 64

// ---------------- scratch (bf16 pairs stored as uint32) ----------------
__device__ uint32_t g_xh [(size_t)B_ROWS * IN_DIM / 2];
__device__ uint32_t g_xl [(size_t)B_ROWS * IN_DIM / 2];
__device__ uint32_t g_weh[(size_t)ZE_NPAD * IN_DIM / 2];
__device__ uint32_t g_wel[(size_t)ZE_NPAD * IN_DIM / 2];
__device__ uint32_t g_w1h[(size_t)VDIM * IN_DIM / 2];
__device__ uint32_t g_w1l[(size_t)VDIM * IN_DIM / 2];
__device__ uint32_t g_w2h[(size_t)2 * VDIM * VDIM / 2];
__device__ uint32_t g_w2l[(size_t)2 * VDIM * VDIM / 2];
__device__ uint32_t g_wdh[(size_t)IN_DIM * CAT_LD / 2];
__device__ uint32_t g_wdl[(size_t)IN_DIM * CAT_LD / 2];
__device__ uint32_t g_hh [(size_t)B_ROWS * VDIM / 2];
__device__ uint32_t g_hl [(size_t)B_ROWS * VDIM / 2];
__device__ uint32_t g_cath[(size_t)B_ROWS * CAT_LD / 2];
__device__ uint32_t g_catl[(size_t)B_ROWS * CAT_LD / 2];
__device__ float g_ml [(size_t)B_ROWS * 2 * VDIM];
__device__ float g_G  [(size_t)KCLS * IN_DIM];
__device__ float g_lb [KCLS];
__device__ float g_klp[B_ROWS];
__device__ float g_ze_s[(size_t)B_ROWS * ENC_DIM];
__device__ float g_zq_s[(size_t)B_ROWS * ENC_DIM];
__device__ float g_lg_s[(size_t)B_ROWS * KCLS];
__device__ float g_kl_s[1];
__device__ int   g_mask_mode;

// ---------------- helpers ----------------
__device__ __forceinline__ uint32_t smem_to_u32(const void* p) {
    uint32_t a;
    asm("{ .reg .u64 t; cvta.to.shared.u64 t, %1; cvt.u32.u64 %0, t; }" : "=r"(a) : "l"(p));
    return a;
}
#define SWZ(b) ((b) ^ (((b) >> 3) & 0x70))
#define CP16(d, s)  asm volatile("cp.async.cg.shared.global [%0], [%1], 16;" :: "r"(d), "l"(s) : "memory")
#define CP_COMMIT() asm volatile("cp.async.commit_group;" ::: "memory")
#define CP_WAIT0()  asm volatile("cp.async.wait_group 0;" ::: "memory")
#define CP_WAIT1()  asm volatile("cp.async.wait_group 1;" ::: "memory")

__device__ __forceinline__ void ldsm_x4(uint32_t* r, uint32_t addr) {
    asm volatile("ldmatrix.sync.aligned.m8n8.x4.shared.b16 {%0,%1,%2,%3}, [%4];"
        : "=r"(r[0]), "=r"(r[1]), "=r"(r[2]), "=r"(r[3]) : "r"(addr));
}
__device__ __forceinline__ void mma16816(float* c, const uint32_t* a, const uint32_t* b) {
    asm volatile("mma.sync.aligned.m16n8k16.row.col.f32.bf16.bf16.f32 "
        "{%0,%1,%2,%3}, {%4,%5,%6,%7}, {%8,%9}, {%0,%1,%2,%3};"
        : "+f"(c[0]), "+f"(c[1]), "+f"(c[2]), "+f"(c[3])
        : "r"(a[0]), "r"(a[1]), "r"(a[2]), "r"(a[3]), "r"(b[0]), "r"(b[1]));
}
// split two fp32 into packed bf16-hi (truncation) + bf16-lo (rn remainder)
__device__ __forceinline__ void split2(float v0, float v1, uint32_t& H, uint32_t& L) {
    uint32_t u0 = __float_as_uint(v0), u1 = __float_as_uint(v1);
    H = __byte_perm(u0, u1, 0x7632);
    float l0 = v0 - __uint_as_float(u0 & 0xFFFF0000u);
    float l1 = v1 - __uint_as_float(u1 & 0xFFFF0000u);
    asm("cvt.rn.bf16x2.f32 %0, %1, %2;" : "=r"(L) : "f"(l1), "f"(l0));
}

// ---------------- pipelined mma.sync bf16x3 GEMM ----------------
// C[M,N] = A[M,K] @ B[N,K]^T + bias. A,B pre-split bf16 hi/lo.
// CTA 128x128, 8 warps, warp tile 64x32, K chunk 64, 2-stage cp.async.
#define ST_BYTES 65536u
#define GEMM_DYN (2 * 65536 + 1024)

__device__ __forceinline__ void load_chunk(uint32_t base, int tid, int m0, int n0, int k0,
    const uint16_t* Ah, const uint16_t* Al, int lda,
    const uint16_t* Bh, const uint16_t* Bl, int ldb)
{
#pragma unroll
    for (int it = 0; it < 4; it++) {
        int idx = it * 256 + tid;
        int row = idx >> 3, u = idx & 7;
        uint32_t off = SWZ((uint32_t)(row * 128 + u * 16));
        size_t ao = (size_t)(m0 + row) * lda + k0 + u * 8;
        size_t bo = (size_t)(n0 + row) * ldb + k0 + u * 8;
        CP16(base + off,           Ah + ao);
        CP16(base + 16384u + off,  Al + ao);
        CP16(base + 32768u + off,  Bh + bo);
        CP16(base + 49152u + off,  Bl + bo);
    }
}

__global__ __launch_bounds__(256, 1)
void gemm_bf3(const uint16_t* __restrict__ Ah, const uint16_t* __restrict__ Al, int lda,
              const uint16_t* __restrict__ Bh, const uint16_t* __restrict__ Bl, int ldb,
              const float* __restrict__ bias,
              float* __restrict__ Cf, uint16_t* __restrict__ Ch, uint16_t* __restrict__ Cl,
              int ldc, int nOut, int K, int relu, int mode)
{
    extern __shared__ char smem[];
    const uint32_t tiles = (smem_to_u32(smem) + 1023) & ~1023u;
    const int tid = threadIdx.x, wid = tid >> 5, lane = tid & 31;
    const int m0 = blockIdx.y * 128, n0 = blockIdx.x * 128;
    const int wm = (wid >> 2) * 64, wn = (wid & 3) * 32;

    float acc[4][4][4];
#pragma unroll
    for (int i = 0; i < 4; i++)
#pragma unroll
        for (int j = 0; j < 4; j++)
#pragma unroll
            for (int q = 0; q < 4; q++) acc[i][j][q] = 0.f;

    const uint32_t aRowByte = (uint32_t)(wm + (lane & 15)) * 128u;
    const uint32_t aKoff    = (uint32_t)((lane >> 4) * 16);
    const uint32_t bRowByte = (uint32_t)(wn + (lane & 7) + ((lane >> 4) << 3)) * 128u;
    const uint32_t bKoff    = (uint32_t)(((lane >> 3) & 1) * 16);

    const int S = K / 64;
    load_chunk(tiles, tid, m0, n0, 0, Ah, Al, lda, Bh, Bl, ldb);
    CP_COMMIT();

    for (int s = 0; s < S; s++) {
        if (s + 1 < S) {
            load_chunk(tiles + ((s + 1) & 1) * ST_BYTES, tid, m0, n0, (s + 1) * 64,
                       Ah, Al, lda, Bh, Bl, ldb);
            CP_COMMIT();
            CP_WAIT1();
        } else {
            CP_WAIT0();
        }
        __syncthreads();

        const uint32_t pah = tiles + (s & 1) * ST_BYTES;
        const uint32_t pal = pah + 16384u, pbh = pah + 32768u, pbl = pah + 49152u;
#pragma unroll
        for (int kk = 0; kk < 4; kk++) {
            const uint32_t kb = (uint32_t)(kk * 32);
            uint32_t ah[4][4], al[4][4], bh[2][4], bl[2][4];
#pragma unroll
            for (int mt = 0; mt < 4; mt++) {
                uint32_t ro = SWZ(aRowByte + (uint32_t)(mt * 2048) + kb + aKoff);
                ldsm_x4(ah[mt], pah + ro);
                ldsm_x4(al[mt], pal + ro);
            }
#pragma unroll
            for (int nb = 0; nb < 2; nb++) {
                uint32_t ro = SWZ(bRowByte + (uint32_t)(nb * 2048) + kb + bKoff);
                ldsm_x4(bh[nb], pbh + ro);
                ldsm_x4(bl[nb], pbl + ro);
            }
#pragma unroll
            for (int mt = 0; mt < 4; mt++)
#pragma unroll
                for (int nt = 0; nt < 4; nt++) {
                    const uint32_t* bhp = &bh[nt >> 1][(nt & 1) * 2];
                    const uint32_t* blp = &bl[nt >> 1][(nt & 1) * 2];
                    mma16816(acc[mt][nt], ah[mt], bhp);
                    mma16816(acc[mt][nt], al[mt], bhp);
                    mma16816(acc[mt][nt], ah[mt], blp);
                }
        }
        __syncthreads();
    }

    // ---- epilogue ----
    if (mode == 0) {
#pragma unroll
        for (int mt = 0; mt < 4; mt++) {
            const int r0 = m0 + wm + mt * 16 + (lane >> 2);
            float* crow0 = Cf + (size_t)r0 * ldc;
            float* crow8 = Cf + (size_t)(r0 + 8) * ldc;
#pragma unroll
            for (int nt = 0; nt < 4; nt++) {
                const int c = n0 + wn + nt * 8 + (lane & 3) * 2;
                if (c >= nOut) continue;
                float b0 = bias[c], b1 = bias[c + 1];
                float v0 = acc[mt][nt][0] + b0, v1 = acc[mt][nt][1] + b1;
                float v2 = acc[mt][nt][2] + b0, v3 = acc[mt][nt][3] + b1;
                if (relu) {
                    v0 = fmaxf(v0, 0.f); v1 = fmaxf(v1, 0.f);
                    v2 = fmaxf(v2, 0.f); v3 = fmaxf(v3, 0.f);
                }
                *reinterpret_cast<float2*>(crow0 + c) = make_float2(v0, v1);
                *reinterpret_cast<float2*>(crow8 + c) = make_float2(v2, v3);
            }
        }
    } else {
#pragma unroll
        for (int mt = 0; mt < 4; mt++) {
            const int r0 = m0 + wm + mt * 16 + (lane >> 2);
#pragma unroll
            for (int nt = 0; nt < 4; nt++) {
                const int c = n0 + wn + nt * 8 + (lane & 3) * 2;
                float b0 = bias[c], b1 = bias[c + 1];
                float v0 = acc[mt][nt][0] + b0, v1 = acc[mt][nt][1] + b1;
                float v2 = acc[mt][nt][2] + b0, v3 = acc[mt][nt][3] + b1;
                if (relu) {
                    v0 = fmaxf(v0, 0.f); v1 = fmaxf(v1, 0.f);
                    v2 = fmaxf(v2, 0.f); v3 = fmaxf(v3, 0.f);
                }
                uint32_t H, L;
                split2(v0, v1, H, L);
                *reinterpret_cast<uint32_t*>(Ch + (size_t)r0 * ldc + c) = H;
                *reinterpret_cast<uint32_t*>(Cl + (size_t)r0 * ldc + c) = L;
                split2(v2, v3, H, L);
                *reinterpret_cast<uint32_t*>(Ch + (size_t)(r0 + 8) * ldc + c) = H;
                *reinterpret_cast<uint32_t*>(Cl + (size_t)(r0 + 8) * ldc + c) = L;
            }
        }
    }
}

// ---------------- fp32 SGEMM (logits only) ----------------
#define BM 128
#define BN 128
#define BK 16
__global__ __launch_bounds__(256, 2)
void sgemm_tn(const float* __restrict__ A, int lda,
              const float* __restrict__ Bm, int ldb,
              const float* __restrict__ bias,
              float* __restrict__ C, int ldc, int M, int N, int K)
{
    __shared__ float As[BK][BM];
    __shared__ float Bs[BK][BN];
    const int tid = threadIdx.x;
    const int m0 = blockIdx.y * BM, n0 = blockIdx.x * BN;
    const int tx = tid & 15, ty = tid >> 4;
    float acc[8][8];
#pragma unroll
    for (int i = 0; i < 8; i++)
#pragma unroll
        for (int j = 0; j < 8; j++) acc[i][j] = 0.f;
    const int lrow = tid >> 2, lkq = (tid & 3) * 4;
    for (int k0 = 0; k0 < K; k0 += BK) {
#pragma unroll
        for (int h = 0; h < 2; h++) {
            int row = lrow + h * 64, gr = m0 + row, kk = k0 + lkq;
            float4 v = make_float4(0.f, 0.f, 0.f, 0.f);
            if (gr < M) v = *reinterpret_cast<const float4*>(A + (size_t)gr * lda + kk);
            As[lkq + 0][row] = v.x; As[lkq + 1][row] = v.y;
            As[lkq + 2][row] = v.z; As[lkq + 3][row] = v.w;
        }
#pragma unroll
        for (int h = 0; h < 2; h++) {
            int row = lrow + h * 64, gr = n0 + row, kk = k0 + lkq;
            float4 v = make_float4(0.f, 0.f, 0.f, 0.f);
            if (gr < N) v = *reinterpret_cast<const float4*>(Bm + (size_t)gr * ldb + kk);
            Bs[lkq + 0][row] = v.x; Bs[lkq + 1][row] = v.y;
            Bs[lkq + 2][row] = v.z; Bs[lkq + 3][row] = v.w;
        }
        __syncthreads();
#pragma unroll
        for (int k = 0; k < BK; k++) {
            float4 a0 = *reinterpret_cast<const float4*>(&As[k][ty * 4]);
            float4 a1 = *reinterpret_cast<const float4*>(&As[k][64 + ty * 4]);
            float4 b0 = *reinterpret_cast<const float4*>(&Bs[k][tx * 4]);
            float4 b1 = *reinterpret_cast<const float4*>(&Bs[k][64 + tx * 4]);
            float a[8] = {a0.x, a0.y, a0.z, a0.w, a1.x, a1.y, a1.z, a1.w};
            float b[8] = {b0.x, b0.y, b0.z, b0.w, b1.x, b1.y, b1.z, b1.w};
#pragma unroll
            for (int i = 0; i < 8; i++)
#pragma unroll
                for (int j = 0; j < 8; j++)
                    acc[i][j] = fmaf(a[i], b[j], acc[i][j]);
        }
        __syncthreads();
    }
#pragma unroll
    for (int i = 0; i < 8; i++) {
        int row = m0 + ((i < 4) ? (ty * 4 + i) : (64 + ty * 4 + i - 4));
        if (row >= M) continue;
#pragma unroll
        for (int j = 0; j < 8; j++) {
            int col = n0 + ((j < 4) ? (tx * 4 + j) : (64 + tx * 4 + j - 4));
            if (col < N) C[(size_t)row * ldc + col] = acc[i][j] + bias[col];
        }
    }
}

// ---------------- prep kernels ----------------
__global__ void split_mat(const float* __restrict__ src, uint32_t* __restrict__ dh,
                          uint32_t* __restrict__ dl, long nPairs, long srcPairs)
{
    long i = (long)blockIdx.x * blockDim.x + threadIdx.x;
    if (i >= nPairs) return;
    float v0 = 0.f, v1 = 0.f;
    if (i < srcPairs) {
        float2 v = reinterpret_cast<const float2*>(src)[i];
        v0 = v.x; v1 = v.y;
    }
    uint32_t H, L;
    split2(v0, v1, H, L);
    dh[i] = H; dl[i] = L;
}

__global__ void split_wd(const float* __restrict__ Wd)
{
    int i = blockIdx.x * blockDim.x + threadIdx.x;
    const int pairsPerRow = CAT_LD / 2;
    if (i >= IN_DIM * pairsPerRow) return;
    int r = i / pairsPerRow, p = i - r * pairsPerRow;
    int c0 = 2 * p;
    float v0 = (c0 < CAT_RAW) ? Wd[(size_t)r * CAT_RAW + c0] : 0.f;
    float v1 = (c0 + 1 < CAT_RAW) ? Wd[(size_t)r * CAT_RAW + c0 + 1] : 0.f;
    uint32_t H, L;
    split2(v0, v1, H, L);
    g_wdh[i] = H; g_wdl[i] = L;
}

__global__ void build_G(const float* __restrict__ W_enc, const float* __restrict__ cb)
{
    int c = blockIdx.x;
    int i = blockIdx.y * 128 + threadIdx.x;
    float s = 0.f;
#pragma unroll 4
    for (int d = 0; d < ENC_DIM; d++)
        s = fmaf(cb[c * ENC_DIM + d], W_enc[(size_t)d * IN_DIM + i], s);
    g_G[(size_t)c * IN_DIM + i] = s;
}
__global__ void build_lb(const float* __restrict__ b_enc, const float* __restrict__ cb)
{
    int c = blockIdx.x;
    int t = threadIdx.x;
    float s = 0.f;
    for (int d = t; d < ENC_DIM; d += 128) s = fmaf(b_enc[d], cb[c * ENC_DIM + d], s);
    __shared__ float sm[128];
    sm[t] = s;
    __syncthreads();
    for (int st = 64; st > 0; st >>= 1) { if (t < st) sm[t] += sm[t + st]; __syncthreads(); }
    if (t == 0) g_lb[c] = sm[0];
}

__global__ void detect_mask_kernel(const unsigned int* __restrict__ w)
{
    __shared__ int s_int, s_flt;
    if (threadIdx.x == 0) { s_int = 1; s_flt = 1; }
    __syncthreads();
    int li = 1, lf = 1;
    for (int i = threadIdx.x; i < 4096; i += blockDim.x) {
        unsigned v = w[i];
        if (v > 1u) li = 0;
        if (v != 0u && v != 0x3F800000u) lf = 0;
    }
    if (!li) atomicAnd(&s_int, 0);
    if (!lf) atomicAnd(&s_flt, 0);
    __syncthreads();
    if (threadIdx.x == 0) g_mask_mode = s_int ? 1 : (s_flt ? 2 : 0);
}

// argmax + softmax + one-hot (into cat hi/lo) + codebook gather
__global__ void argmax_y_kernel(const float* __restrict__ logits,
                                const void* __restrict__ mask,
                                const int* __restrict__ labels,
                                const float* __restrict__ codebook,
                                float* __restrict__ zq)
{
    const int b = blockIdx.x;
    const int lane = threadIdx.x;
    const float NEG = __int_as_float(0xff800000u);
    const float* lr = logits + (size_t)b * KCLS;
    const int k0 = 2 * lane, k1 = 2 * lane + 1;
    float va = (k0 < KCLS) ? lr[k0] : NEG;
    float vb = (k1 < KCLS) ? lr[k1] : NEG;
    float m; int mi;
    if (va >= vb) { m = va; mi = k0; } else { m = vb; mi = k1; }
#pragma unroll
    for (int off = 16; off > 0; off >>= 1) {
        float om = __shfl_xor_sync(0xffffffffu, m, off);
        int oi = __shfl_xor_sync(0xffffffffu, mi, off);
        if (om > m || (om == m && oi < mi)) { m = om; mi = oi; }
    }
    float ea = (k0 < KCLS) ? expf(va - m) : 0.f;
    float eb = (k1 < KCLS) ? expf(vb - m) : 0.f;
    float s = ea + eb;
#pragma unroll
    for (int off = 16; off > 0; off >>= 1) s += __shfl_xor_sync(0xffffffffu, s, off);
    float inv = 1.0f / s;

    int mode = g_mask_mode;
    bool known;
    if (mode == 1)      known = ((const int*)mask)[b] != 0;
    else if (mode == 2) known = ((const float*)mask)[b] != 0.f;
    else                known = ((const unsigned char*)mask)[b] != 0;
    int lab = labels[b];

    float y0 = (k0 < KCLS) ? (known ? (k0 == lab ? 1.f : 0.f) : ea * inv) : 0.f;
    float y1 = (k1 < KCLS) ? (known ? (k1 == lab ? 1.f : 0.f) : eb * inv) : 0.f;
    uint32_t H, L;
    split2(y0, y1, H, L);
    const size_t pi = (size_t)b * (CAT_LD / 2) + (VDIM / 2) + lane;
    g_cath[pi] = H; g_catl[pi] = L;

    const float* cr = codebook + (size_t)mi * ENC_DIM;
    float* zr = zq + (size_t)b * ENC_DIM;
    for (int i = lane; i < ENC_DIM; i += 32) zr[i] = cr[i];
}

// reparam sample (into cat hi/lo) + KL partial
__global__ void vae_post_kernel(const float* __restrict__ eps)
{
    const int b = blockIdx.x;
    const int t = threadIdx.x;
    const float* mlr = g_ml + (size_t)b * (2 * VDIM);
    const float* er = eps + (size_t)b * VDIM;
    float kl = 0.f;
#pragma unroll
    for (int p = t; p < VDIM / 2; p += 256) {
        int i0 = 2 * p;
        float mu0 = mlr[i0], mu1 = mlr[i0 + 1];
        float lv0 = mlr[VDIM + i0], lv1 = mlr[VDIM + i0 + 1];
        kl += 0.5f * (expf(lv0) + mu0 * mu0 - 1.0f - lv0);
        kl += 0.5f * (expf(lv1) + mu1 * mu1 - 1.0f - lv1);
        float v0 = fmaf(expf(0.5f * lv0), er[i0], mu0);
        float v1 = fmaf(expf(0.5f * lv1), er[i0 + 1], mu1);
        uint32_t H, L;
        split2(v0, v1, H, L);
        const size_t pi = (size_t)b * (CAT_LD / 2) + p;
        g_cath[pi] = H; g_catl[pi] = L;
    }
    __shared__ float sm[256];
    sm[t] = kl;
    __syncthreads();
    for (int st = 128; st > 0; st >>= 1) { if (t < st) sm[t] += sm[t + st]; __syncthreads(); }
    if (t == 0) g_klp[b] = sm[0];
}

__global__ void kl_reduce_kernel(float* __restrict__ out)
{
    const int t = threadIdx.x;
    float s = 0.f;
    for (int i = t; i < B_ROWS; i += 256) s += g_klp[i];
    __shared__ float sm[256];
    sm[t] = s;
    __syncthreads();
    for (int st = 128; st > 0; st >>= 1) { if (t < st) sm[t] += sm[t + st]; __syncthreads(); }
    if (t == 0) *out = sm[0] / (float)B_ROWS;
}

// ---------------- host ----------------
static void launch_gemm(const void* Ah, const void* Al, int lda,
                        const void* Bh, const void* Bl, int ldb,
                        const float* bias, float* Cf, void* Ch, void* Cl,
                        int ldc, int nPad, int nOut, int K, int relu, int mode)
{
    cudaFuncSetAttribute(gemm_bf3, cudaFuncAttributeMaxDynamicSharedMemorySize, GEMM_DYN);
    dim3 grid(nPad / 128, B_ROWS / 128);
    gemm_bf3<<<grid, 256, GEMM_DYN>>>(
        (const uint16_t*)Ah, (const uint16_t*)Al, lda,
        (const uint16_t*)Bh, (const uint16_t*)Bl, ldb,
        bias, Cf, (uint16_t*)Ch, (uint16_t*)Cl, ldc, nOut, K, relu, mode);
}

extern "C" void kernel_launch(void* const* d_in, const int* in_sizes, int n_in,
                              void* d_out, int out_size)
{
    const float* x        = (const float*)d_in[0];
    const void*  mask     = d_in[1];
    const int*   labels   = (const int*)d_in[2];
    const float* eps      = (const float*)d_in[3];
    const float* W_enc    = (const float*)d_in[4];
    const float* b_enc    = (const float*)d_in[5];
    const float* codebook = (const float*)d_in[6];
    const float* W1       = (const float*)d_in[7];
    const float* b1       = (const float*)d_in[8];
    const float* W2       = (const float*)d_in[9];
    const float* b2       = (const float*)d_in[10];
    const float* Wd       = (const float*)d_in[11];
    const float* bd       = (const float*)d_in[12];
    float* out = (float*)d_out;

    void *p_xh, *p_xl, *p_weh, *p_wel, *p_w1h, *p_w1l, *p_w2h, *p_w2l, *p_wdh, *p_wdl;
    void *p_hh, *p_hl, *p_cath, *p_catl;
    float *p_ml, *p_G, *p_lb, *p_ze, *p_zq, *p_lg, *p_kl;
    cudaGetSymbolAddress(&p_xh, g_xh);   cudaGetSymbolAddress(&p_xl, g_xl);
    cudaGetSymbolAddress(&p_weh, g_weh); cudaGetSymbolAddress(&p_wel, g_wel);
    cudaGetSymbolAddress(&p_w1h, g_w1h); cudaGetSymbolAddress(&p_w1l, g_w1l);
    cudaGetSymbolAddress(&p_w2h, g_w2h); cudaGetSymbolAddress(&p_w2l, g_w2l);
    cudaGetSymbolAddress(&p_wdh, g_wdh); cudaGetSymbolAddress(&p_wdl, g_wdl);
    cudaGetSymbolAddress(&p_hh, g_hh);   cudaGetSymbolAddress(&p_hl, g_hl);
    cudaGetSymbolAddress(&p_cath, g_cath); cudaGetSymbolAddress(&p_catl, g_catl);
    cudaGetSymbolAddress((void**)&p_ml, g_ml);
    cudaGetSymbolAddress((void**)&p_G,  g_G);
    cudaGetSymbolAddress((void**)&p_lb, g_lb);
    cudaGetSymbolAddress((void**)&p_ze, g_ze_s);
    cudaGetSymbolAddress((void**)&p_zq, g_zq_s);
    cudaGetSymbolAddress((void**)&p_lg, g_lg_s);
    cudaGetSymbolAddress((void**)&p_kl, g_kl_s);

    const size_t full_elems = (size_t)B_ROWS * (IN_DIM + ENC_DIM + ENC_DIM + KCLS) + 1;
    const bool full = ((size_t)out_size >= full_elems);
    float* xt = out;
    float* ze = full ? out + (size_t)B_ROWS * IN_DIM : p_ze;
    float* zq = full ? ze + (size_t)B_ROWS * ENC_DIM : p_zq;
    float* lg = full ? zq + (size_t)B_ROWS * ENC_DIM : p_lg;
    float* kl = full ? lg + (size_t)B_ROWS * KCLS    : p_kl;

    // ---- prep: splits + logits weights + mask mode ----
    {
        long np = (long)B_ROWS * IN_DIM / 2;
        split_mat<<<(unsigned)((np + 255) / 256), 256>>>(x, (uint32_t*)p_xh, (uint32_t*)p_xl, np, np);
        long sp = (long)ENC_DIM * IN_DIM / 2, tp = (long)ZE_NPAD * IN_DIM / 2;
        split_mat<<<(unsigned)((tp + 255) / 256), 256>>>(W_enc, (uint32_t*)p_weh, (uint32_t*)p_wel, tp, sp);
        long w1p = (long)VDIM * IN_DIM / 2;
        split_mat<<<(unsigned)((w1p + 255) / 256), 256>>>(W1, (uint32_t*)p_w1h, (uint32_t*)p_w1l, w1p, w1p);
        long w2p = (long)2 * VDIM * VDIM / 2;
        split_mat<<<(unsigned)((w2p + 255) / 256), 256>>>(W2, (uint32_t*)p_w2h, (uint32_t*)p_w2l, w2p, w2p);
        split_wd<<<(IN_DIM * (CAT_LD / 2) + 255) / 256, 256>>>(Wd);
    }
    detect_mask_kernel<<<1, 256>>>((const unsigned int*)mask);
    build_G<<<dim3(KCLS, IN_DIM / 128), 128>>>(W_enc, codebook);
    build_lb<<<KCLS, 128>>>(b_enc, codebook);

    // logits (exact fp32 via G = codebook @ W_enc)
    {
        dim3 grid(1, B_ROWS / BM);
        sgemm_tn<<<grid, 256>>>(x, IN_DIM, p_G, IN_DIM, p_lb, lg, KCLS, B_ROWS, KCLS, IN_DIM);
    }

    // z_e_x
    launch_gemm(p_xh, p_xl, IN_DIM, p_weh, p_wel, IN_DIM, b_enc,
                ze, nullptr, nullptr, ENC_DIM, ZE_NPAD, ENC_DIM, IN_DIM, 0, 0);
    // h = relu(x@W1^T + b1) -> bf16 hi/lo
    launch_gemm(p_xh, p_xl, IN_DIM, p_w1h, p_w1l, IN_DIM, b1,
                nullptr, p_hh, p_hl, VDIM, VDIM, VDIM, IN_DIM, 1, 1);
    // mu||logvar
    launch_gemm(p_hh, p_hl, VDIM, p_w2h, p_w2l, VDIM, b2,
                p_ml, nullptr, nullptr, 2 * VDIM, 2 * VDIM, 2 * VDIM, VDIM, 0, 0);

    // argmax / y / z_q (fills cat y region)
    argmax_y_kernel<<<B_ROWS, 32>>>(lg, mask, labels, codebook, zq);
    // sampled_z (fills cat z region) + KL
    vae_post_kernel<<<B_ROWS, 256>>>(eps);
    kl_reduce_kernel<<<1, 256>>>(kl);

    // decoder
    launch_gemm(p_cath, p_catl, CAT_LD, p_wdh, p_wdl, CAT_LD, bd,
                xt, nullptr, nullptr, IN_DIM, IN_DIM, IN_DIM, CAT_LD, 0, 0);
}